// round 13
// baseline (speedup 1.0000x reference)
#include <cuda_runtime.h>
#include <cstdint>
#include <math.h>

#define BATCH 2
#define SEQ   2048
#define DIM   1024
#define HEADS 16
#define DHEAD 64
#define INNER 1024
#define NREL  (2*SEQ-1)   /* 4095 */
#define LOG2E 1.4426950408889634f

// ---------------- scratch (static device arrays; no allocation) ----------------
__device__ float g_q[BATCH*HEADS*SEQ*DHEAD];      // (b,h,n,d)  tf32-rounded, *0.125
__device__ float g_k[BATCH*HEADS*SEQ*DHEAD];      // tf32-rounded
__device__ float g_v[BATCH*HEADS*SEQ*DHEAD];      // tf32-rounded
__device__ float g_attn[(size_t)BATCH*SEQ*INNER]; // (b,n,inner), tf32-rounded at write
__device__ float g_bias[HEADS*NREL];              // pre-scaled: (bias-12)*log2e
__device__ float g_xr[(size_t)BATCH*SEQ*DIM];     // tf32-rounded X
__device__ float g_wt[(size_t)3072*DIM];          // [Wq|Wkv]^T rows: out-col n, len K=1024, tf32
__device__ float g_wot[(size_t)DIM*INNER];        // Wo^T rows: out-col n, len K=1024, tf32

// ---------------- helpers ----------------
__device__ __forceinline__ float to_tf32(float x) {
    uint32_t y;
    asm("cvt.rna.tf32.f32 %0, %1;" : "=r"(y) : "f"(x));
    return __uint_as_float(y);
}
__device__ __forceinline__ float ex2f(float x) {
    float y; asm("ex2.approx.f32 %0, %1;" : "=f"(y) : "f"(x)); return y;
}
__device__ __forceinline__ void mma8(float* c, float a0, float a1, float a2, float a3,
                                     float b0, float b1) {
    asm volatile(
        "mma.sync.aligned.m16n8k8.row.col.f32.tf32.tf32.f32 "
        "{%0,%1,%2,%3},{%4,%5,%6,%7},{%8,%9},{%0,%1,%2,%3};\n"
        : "+f"(c[0]), "+f"(c[1]), "+f"(c[2]), "+f"(c[3])
        : "r"(__float_as_uint(a0)), "r"(__float_as_uint(a1)),
          "r"(__float_as_uint(a2)), "r"(__float_as_uint(a3)),
          "r"(__float_as_uint(b0)), "r"(__float_as_uint(b1)));
}
__device__ __forceinline__ uint32_t smem_u32(const void* p) {
    uint32_t a;
    asm("{ .reg .u64 t; cvta.to.shared.u64 t, %1; cvt.u32.u64 %0, t; }" : "=r"(a) : "l"(p));
    return a;
}
__device__ __forceinline__ void cp16(uint32_t dst, const float* src) {
    asm volatile("cp.async.ca.shared.global [%0], [%1], 16;" :: "r"(dst), "l"(src));
}
#define CP_COMMIT() asm volatile("cp.async.commit_group;" ::: "memory")
#define CP_WAIT(n)  asm volatile("cp.async.wait_group %0;" :: "n"(n) : "memory")

// ---------------- kernel 0a: T5 relative bias table (pre-scaled for exp2) ------
__global__ void bias_table_kernel(const float* __restrict__ rel_emb) {
    int idx = blockIdx.x * blockDim.x + threadIdx.x;
    if (idx >= HEADS * NREL) return;
    int h = idx / NREL;
    int rel = idx % NREL - (SEQ - 1);   // rel = j - i
    int n = -rel;                        // i - j
    int ret = 0;
    if (n < 0) { ret = 16; n = -n; }
    int bucket;
    if (n < 8) {
        bucket = ret + n;
    } else {
        int v = 8 + (int)(logf((float)n / 8.0f) / logf(16.0f) * 8.0f);
        v = min(v, 15);
        bucket = ret + v;
    }
    g_bias[idx] = (rel_emb[bucket * HEADS + h] - 12.0f) * LOG2E;
}

// ---------------- kernel 0b: round X to tf32 ----------------
__global__ __launch_bounds__(256) void round_x_kernel(const float* __restrict__ X) {
    int i = blockIdx.x * 256 + threadIdx.x;
    float4 v = ((const float4*)X)[i];
    v.x = to_tf32(v.x); v.y = to_tf32(v.y); v.z = to_tf32(v.z); v.w = to_tf32(v.w);
    ((float4*)g_xr)[i] = v;
}

// ---------------- kernel 0c: transpose + round weights --------------------------
__global__ void transpose_round(int dsel, size_t doff, const float* __restrict__ src, int N) {
    __shared__ float t[32][33];
    float* dst = (dsel == 0 ? g_wt : g_wot) + doff;
    int n0 = blockIdx.x * 32, k0 = blockIdx.y * 32;
    int tx = threadIdx.x, ty = threadIdx.y;
#pragma unroll
    for (int j = 0; j < 32; j += 8)
        t[ty + j][tx] = to_tf32(src[(size_t)(k0 + ty + j) * N + n0 + tx]);
    __syncthreads();
#pragma unroll
    for (int j = 0; j < 32; j += 8)
        dst[(size_t)(n0 + ty + j) * DIM + k0 + tx] = t[tx][ty + j];
}

// ======================================================================
// GEMM core (unchanged from 746us run): CTA 128x128, cp.async double-buffered.
// ======================================================================
#define GR 36
#define ABUF(b)  ((b) * 4608)
#define BBUF(b)  (9216 + (b) * 4608)
#define G_SMEM_BYTES 73728

__device__ __forceinline__ void g_stage(uint32_t sbase, int buf,
                                        const float* __restrict__ Asrc,
                                        const float* __restrict__ Bsrc,
                                        int kt, int tid) {
    const int m = tid >> 1, half = tid & 1;
    const float* as = Asrc + (size_t)m * DIM + kt * 32 + half * 16;
    uint32_t ad = sbase + buf * 18432 + m * 144 + half * 64;
#pragma unroll
    for (int c = 0; c < 4; c++) cp16(ad + c * 16, as + c * 4);
    const float* bs = Bsrc + (size_t)m * DIM + kt * 32 + half * 16;
    uint32_t bd = sbase + 36864 + buf * 18432 + m * 144 + half * 64;
#pragma unroll
    for (int c = 0; c < 4; c++) cp16(bd + c * 16, bs + c * 4);
}

__device__ __forceinline__ void g_mainloop(float* smem, uint32_t sbase,
                                           const float* Asrc, const float* Bsrc,
                                           float acc[2][8][4],
                                           int tid, int wm, int wn, int g, int tg) {
    g_stage(sbase, 0, Asrc, Bsrc, 0, tid);
    CP_COMMIT();
    for (int kt = 0; kt < 32; kt++) {
        int buf = kt & 1;
        if (kt + 1 < 32) {
            g_stage(sbase, buf ^ 1, Asrc, Bsrc, kt + 1, tid);
            CP_COMMIT();
            CP_WAIT(1);
        } else {
            CP_WAIT(0);
        }
        __syncthreads();
        const float* As = smem + ABUF(buf);
        const float* Bs = smem + BBUF(buf);
#pragma unroll
        for (int kk = 0; kk < 4; kk++) {
            float aF[2][4]; float bF[8][2];
#pragma unroll
            for (int mt = 0; mt < 2; mt++) {
                int r = wm * 32 + mt * 16 + g;
                aF[mt][0] = As[r * GR + kk * 8 + tg];
                aF[mt][1] = As[(r + 8) * GR + kk * 8 + tg];
                aF[mt][2] = As[r * GR + kk * 8 + tg + 4];
                aF[mt][3] = As[(r + 8) * GR + kk * 8 + tg + 4];
            }
#pragma unroll
            for (int nt = 0; nt < 8; nt++) {
                int c = wn * 64 + nt * 8 + g;
                bF[nt][0] = Bs[c * GR + kk * 8 + tg];
                bF[nt][1] = Bs[c * GR + kk * 8 + tg + 4];
            }
#pragma unroll
            for (int mt = 0; mt < 2; mt++)
#pragma unroll
                for (int nt = 0; nt < 8; nt++)
                    mma8(acc[mt][nt], aF[mt][0], aF[mt][1], aF[mt][2], aF[mt][3],
                         bF[nt][0], bF[nt][1]);
        }
        __syncthreads();
    }
}

// ---------------- kernel 1: fused QKV projection ----------------
__global__ __launch_bounds__(256, 2) void gemm_qkv2() {
    extern __shared__ __align__(16) float smem[];
    uint32_t sbase = smem_u32(smem);
    const int tid = threadIdx.x;
    const int warp = tid >> 5, lane = tid & 31;
    const int wm = warp >> 1, wn = warp & 1;
    const int g = lane >> 2, tg = lane & 3;
    const int row0 = blockIdx.y * 128, ncol0 = blockIdx.x * 128;

    float acc[2][8][4];
#pragma unroll
    for (int a = 0; a < 2; a++)
#pragma unroll
        for (int b = 0; b < 8; b++)
#pragma unroll
            for (int c = 0; c < 4; c++) acc[a][b][c] = 0.f;

    g_mainloop(smem, sbase, g_xr + (size_t)row0 * DIM, g_wt + (size_t)ncol0 * DIM,
               acc, tid, wm, wn, g, tg);

    // scatter into (b,h,n,d), tf32-rounded (q *0.125: exact pow2 scale commutes
    // bit-exactly with tf32 rounding)
#pragma unroll
    for (int mt = 0; mt < 2; mt++) {
        int r0 = row0 + wm * 32 + mt * 16 + g;
        int bb = r0 >> 11;
        int ii = r0 & 2047;
#pragma unroll
        for (int nt = 0; nt < 8; nt++) {
            int c0 = ncol0 + wn * 64 + nt * 8 + 2 * tg;
            int reg2 = c0 >> 10;          // 0:q 1:k 2:v
            int c = c0 & 1023;
            int h = c >> 6, dd = c & 63;
            float* base = (reg2 == 0) ? g_q : ((reg2 == 1) ? g_k : g_v);
            float s = (reg2 == 0) ? 0.125f : 1.0f;
            size_t o0 = (((size_t)(bb * HEADS + h) * SEQ) + ii) * DHEAD + dd;
            *(float2*)(base + o0) =
                make_float2(to_tf32(acc[mt][nt][0]) * s, to_tf32(acc[mt][nt][1]) * s);
            *(float2*)(base + o0 + 512) =
                make_float2(to_tf32(acc[mt][nt][2]) * s, to_tf32(acc[mt][nt][3]) * s);
        }
    }
}

// ---------------- kernel 3: output projection + bias ----------------
__global__ __launch_bounds__(256, 2) void gemm_out2(
    const float* __restrict__ bo, float* __restrict__ out) {
    extern __shared__ __align__(16) float smem[];
    uint32_t sbase = smem_u32(smem);
    const int tid = threadIdx.x;
    const int warp = tid >> 5, lane = tid & 31;
    const int wm = warp >> 1, wn = warp & 1;
    const int g = lane >> 2, tg = lane & 3;
    const int row0 = blockIdx.y * 128, ncol0 = blockIdx.x * 128;

    float acc[2][8][4];
#pragma unroll
    for (int a = 0; a < 2; a++)
#pragma unroll
        for (int b = 0; b < 8; b++)
#pragma unroll
            for (int c = 0; c < 4; c++) acc[a][b][c] = 0.f;

    g_mainloop(smem, sbase, g_attn + (size_t)row0 * INNER, g_wot + (size_t)ncol0 * DIM,
               acc, tid, wm, wn, g, tg);

#pragma unroll
    for (int mt = 0; mt < 2; mt++) {
        int r0 = row0 + wm * 32 + mt * 16 + g;
#pragma unroll
        for (int nt = 0; nt < 8; nt++) {
            int c0 = ncol0 + wn * 64 + nt * 8 + 2 * tg;
            float b0 = bo[c0], b1 = bo[c0 + 1];
            *(float2*)(out + (size_t)r0 * DIM + c0)       = make_float2(acc[mt][nt][0] + b0, acc[mt][nt][1] + b1);
            *(float2*)(out + (size_t)(r0 + 8) * DIM + c0) = make_float2(acc[mt][nt][2] + b0, acc[mt][nt][3] + b1);
        }
    }
}

// ======================================================================
// kernel 2: flash attention — 128 q-rows/CTA, 2 CTAs/SM (smem 110,592 B).
// 8 warps x 16 rows. Inputs pre-rounded tf32 (q pre-scaled 0.125): no cvts
// in staging. Fragment arrays split in halves to stay under 128 regs.
// ======================================================================
#define FROW 72
#define FLASH_SMEM_FLOATS ((128 + 128 + 64 + 64) * FROW)   /* 27648 -> 110,592 B */

__global__ __launch_bounds__(256, 2) void flash_attn()
{
    extern __shared__ __align__(16) float fsmem[];
    float* Qs = fsmem;             // 128 x 72
    float* Ps = Qs + 128 * FROW;   // 128 x 72
    float* Ks = Ps + 128 * FROW;   // 64 x 72
    float* Vs = Ks + 64 * FROW;    // 64 x 72

    const int qb = blockIdx.x, bh = blockIdx.y;
    const int b = bh >> 4, h = bh & 15;
    const int tid = threadIdx.x, warp = tid >> 5, lane = tid & 31;
    const int g = lane >> 2, tg = lane & 3;

    const float* qptr = g_q + ((size_t)bh * SEQ + qb * 128) * DHEAD;
    const float* kptr = g_k + (size_t)bh * SEQ * DHEAD;
    const float* vptr = g_v + (size_t)bh * SEQ * DHEAD;

    // stage Q: 128 rows x 64 d = 2048 float4 -> 8 iters of 256 threads
#pragma unroll
    for (int i = 0; i < 8; i++) {
        int f = tid + i * 256;
        int row = f >> 4, d0 = (f & 15) << 2;
        float4 v = *(const float4*)(qptr + row * DHEAD + d0);
        float* dst = Qs + row * FROW;
        int q4 = d0 >> 2;
        dst[q4]            = v.x;
        dst[16 + q4]       = v.y;
        dst[(32 + q4) ^ 4] = v.z;
        dst[(48 + q4) ^ 4] = v.w;
    }

    float oa[8][4];
#pragma unroll
    for (int nt = 0; nt < 8; nt++)
#pragma unroll
        for (int c = 0; c < 4; c++) oa[nt][c] = 0.f;
    float lsum[2] = {0.f, 0.f};

    const float* btab = g_bias + h * NREL + (SEQ - 1);
    const int iG = qb * 128 + warp * 16 + g;   // global q row (low half)
    const int r0 = warp * 16 + g;              // local row (low half)

    for (int t = 0; t < SEQ / 64; t++) {
        // stage K/V tile: 64x64 each -> 4 iters of 256 threads
#pragma unroll
        for (int i = 0; i < 4; i++) {
            int f = tid + i * 256;
            int key = f >> 4, d0 = (f & 15) << 2;
            int q4 = d0 >> 2;
            float4 kv = *(const float4*)(kptr + (size_t)t * 64 * DHEAD + key * DHEAD + d0);
            float* kd = Ks + key * FROW;
            kd[q4]            = kv.x;
            kd[16 + q4]       = kv.y;
            kd[(32 + q4) ^ 4] = kv.z;
            kd[(48 + q4) ^ 4] = kv.w;
            float4 vv = *(const float4*)(vptr + (size_t)t * 64 * DHEAD + key * DHEAD + d0);
            int vpos = (((key & 3) << 4) + (key >> 2)) ^ ((key & 2) << 1);
            Vs[(d0 + 0) * FROW + vpos] = vv.x;
            Vs[(d0 + 1) * FROW + vpos] = vv.y;
            Vs[(d0 + 2) * FROW + vpos] = vv.z;
            Vs[(d0 + 3) * FROW + vpos] = vv.w;
        }
        __syncthreads();

        // ---- S = Q K^T ----
        float sc[8][4];
#pragma unroll
        for (int nt = 0; nt < 8; nt++)
#pragma unroll
            for (int c = 0; c < 4; c++) sc[nt][c] = 0.f;
#pragma unroll
        for (int p = 0; p < 4; p++) {
            int off = (tg * 16 + 4 * p) ^ ((tg & 2) << 1);
            float4 qLo = *(const float4*)(Qs + r0 * FROW + off);
            float4 qHi = *(const float4*)(Qs + (r0 + 8) * FROW + off);
#pragma unroll
            for (int half = 0; half < 2; half++) {
                float4 kf[4];
#pragma unroll
                for (int j = 0; j < 4; j++)
                    kf[j] = *(const float4*)(Ks + ((half * 4 + j) * 8 + g) * FROW + off);
#pragma unroll
                for (int j = 0; j < 4; j++) {
                    int nt = half * 4 + j;
                    mma8(sc[nt], qLo.x, qHi.x, qLo.y, qHi.y, kf[j].x, kf[j].y);
                    mma8(sc[nt], qLo.z, qHi.z, qLo.w, qHi.w, kf[j].z, kf[j].w);
                }
            }
        }

        // ---- bias + exp (fixed shift) + row-sum + store P (permuted) ----
        {
            const float* bt0 = btab + t * 64 - iG;
            const float* bt1 = bt0 - 8;
#pragma unroll
            for (int nt = 0; nt < 8; nt++) {
                int c = nt * 8 + 2 * tg;
                int pos0 = (((c & 3) << 4) + (c >> 2)) ^ ((c & 2) << 1);
                int c1 = c + 1;
                int pos1 = ((((c1) & 3) << 4) + (c1 >> 2)) ^ ((c1 & 2) << 1);
                float p0 = to_tf32(ex2f(fmaf(sc[nt][0], LOG2E, bt0[c])));
                float p1 = to_tf32(ex2f(fmaf(sc[nt][1], LOG2E, bt0[c1])));
                float p2 = to_tf32(ex2f(fmaf(sc[nt][2], LOG2E, bt1[c])));
                float p3 = to_tf32(ex2f(fmaf(sc[nt][3], LOG2E, bt1[c1])));
                lsum[0] += p0 + p1;
                lsum[1] += p2 + p3;
                Ps[r0 * FROW + pos0]       = p0;
                Ps[r0 * FROW + pos1]       = p1;
                Ps[(r0 + 8) * FROW + pos0] = p2;
                Ps[(r0 + 8) * FROW + pos1] = p3;
            }
        }
        __syncwarp();

        // ---- O += P @ V ----
#pragma unroll
        for (int p = 0; p < 4; p++) {
            int off = (tg * 16 + 4 * p) ^ ((tg & 2) << 1);
            float4 pLo = *(const float4*)(Ps + r0 * FROW + off);
            float4 pHi = *(const float4*)(Ps + (r0 + 8) * FROW + off);
#pragma unroll
            for (int half = 0; half < 2; half++) {
                float4 vf[4];
#pragma unroll
                for (int j = 0; j < 4; j++)
                    vf[j] = *(const float4*)(Vs + ((half * 4 + j) * 8 + g) * FROW + off);
#pragma unroll
                for (int j = 0; j < 4; j++) {
                    int nt = half * 4 + j;
                    mma8(oa[nt], pLo.x, pHi.x, pLo.y, pHi.y, vf[j].x, vf[j].y);
                    mma8(oa[nt], pLo.z, pHi.z, pLo.w, pHi.w, vf[j].z, vf[j].w);
                }
            }
        }
        __syncthreads();
    }

    // ---- epilogue: normalize, tf32-round, write (b, n, h*d) ----
    float* obase = g_attn + (size_t)b * SEQ * INNER + h * DHEAD;
    float l0 = lsum[0], l1 = lsum[1];
    l0 += __shfl_xor_sync(0xffffffffu, l0, 1);
    l0 += __shfl_xor_sync(0xffffffffu, l0, 2);
    l1 += __shfl_xor_sync(0xffffffffu, l1, 1);
    l1 += __shfl_xor_sync(0xffffffffu, l1, 2);
    float il0 = 1.f / l0, il1 = 1.f / l1;
    int rg = qb * 128 + warp * 16 + g;
#pragma unroll
    for (int nt = 0; nt < 8; nt++) {
        int col = nt * 8 + 2 * tg;
        *(float2*)(obase + (size_t)rg * INNER + col) =
            make_float2(to_tf32(oa[nt][0] * il0), to_tf32(oa[nt][1] * il0));
        *(float2*)(obase + (size_t)(rg + 8) * INNER + col) =
            make_float2(to_tf32(oa[nt][2] * il1), to_tf32(oa[nt][3] * il1));
    }
}

// ---------------- launch ----------------
extern "C" void kernel_launch(void* const* d_in, const int* in_sizes, int n_in,
                              void* d_out, int out_size)
{
    const float* x    = (const float*)d_in[0];
    const float* Wq   = (const float*)d_in[1];
    const float* Wkv  = (const float*)d_in[2];
    const float* Wo   = (const float*)d_in[3];
    const float* bo   = (const float*)d_in[4];
    const float* rel  = (const float*)d_in[5];
    float* out = (float*)d_out;

    const int flash_smem = FLASH_SMEM_FLOATS * (int)sizeof(float); // 110,592 B
    cudaFuncSetAttribute(flash_attn, cudaFuncAttributeMaxDynamicSharedMemorySize, flash_smem);
    cudaFuncSetAttribute(gemm_qkv2, cudaFuncAttributeMaxDynamicSharedMemorySize, G_SMEM_BYTES);
    cudaFuncSetAttribute(gemm_out2, cudaFuncAttributeMaxDynamicSharedMemorySize, G_SMEM_BYTES);

    // prep: bias table, rounded X, transposed+rounded weights
    bias_table_kernel<<<(HEADS * NREL + 255) / 256, 256>>>(rel);
    round_x_kernel<<<BATCH * SEQ * DIM / 4 / 256, 256>>>(x);
    {
        dim3 tb(32, 8);
        transpose_round<<<dim3(DIM / 32, DIM / 32), tb>>>(0, 0, Wq, INNER);
        transpose_round<<<dim3(2 * INNER / 32, DIM / 32), tb>>>(0, (size_t)INNER * DIM, Wkv, 2 * INNER);
        transpose_round<<<dim3(DIM / 32, DIM / 32), tb>>>(1, 0, Wo, DIM);
    }

    gemm_qkv2<<<dim3(24, 32), 256, G_SMEM_BYTES>>>();
    flash_attn<<<dim3(16, 32), 256, flash_smem>>>();
    gemm_out2<<<dim3(8, 32), 256, G_SMEM_BYTES>>>(bo, out);
}

// round 15
// speedup vs baseline: 1.1401x; 1.1401x over previous
#include <cuda_runtime.h>
#include <cstdint>
#include <math.h>

#define BATCH 2
#define SEQ   2048
#define DIM   1024
#define HEADS 16
#define DHEAD 64
#define INNER 1024
#define NREL  (2*SEQ-1)   /* 4095 */
#define LOG2E 1.4426950408889634f

// ---------------- scratch (static device arrays; no allocation) ----------------
__device__ float g_q[BATCH*HEADS*SEQ*DHEAD];      // (b,h,n,d)  tf32-rounded, *0.125
__device__ float g_k[BATCH*HEADS*SEQ*DHEAD];      // tf32-rounded
__device__ float g_v[BATCH*HEADS*SEQ*DHEAD];      // tf32-rounded
__device__ float g_attn[(size_t)BATCH*SEQ*INNER]; // (b,n,inner), tf32-rounded at write
__device__ float g_bias[HEADS*NREL];              // pre-scaled: (bias-12)*log2e
__device__ float g_xr[(size_t)BATCH*SEQ*DIM];     // tf32-rounded X
__device__ float g_wt[(size_t)3072*DIM];          // [Wq|Wkv]^T rows: out-col n, len K=1024, tf32
__device__ float g_wot[(size_t)DIM*INNER];        // Wo^T rows: out-col n, len K=1024, tf32

// ---------------- helpers ----------------
__device__ __forceinline__ float to_tf32(float x) {
    uint32_t y;
    asm("cvt.rna.tf32.f32 %0, %1;" : "=r"(y) : "f"(x));
    return __uint_as_float(y);
}
__device__ __forceinline__ float ex2f(float x) {
    float y; asm("ex2.approx.f32 %0, %1;" : "=f"(y) : "f"(x)); return y;
}
__device__ __forceinline__ void mma8(float* c, float a0, float a1, float a2, float a3,
                                     float b0, float b1) {
    asm volatile(
        "mma.sync.aligned.m16n8k8.row.col.f32.tf32.tf32.f32 "
        "{%0,%1,%2,%3},{%4,%5,%6,%7},{%8,%9},{%0,%1,%2,%3};\n"
        : "+f"(c[0]), "+f"(c[1]), "+f"(c[2]), "+f"(c[3])
        : "r"(__float_as_uint(a0)), "r"(__float_as_uint(a1)),
          "r"(__float_as_uint(a2)), "r"(__float_as_uint(a3)),
          "r"(__float_as_uint(b0)), "r"(__float_as_uint(b1)));
}
__device__ __forceinline__ uint32_t smem_u32(const void* p) {
    uint32_t a;
    asm("{ .reg .u64 t; cvta.to.shared.u64 t, %1; cvt.u32.u64 %0, t; }" : "=r"(a) : "l"(p));
    return a;
}
__device__ __forceinline__ void cp16(uint32_t dst, const float* src) {
    asm volatile("cp.async.ca.shared.global [%0], [%1], 16;" :: "r"(dst), "l"(src));
}
#define CP_COMMIT() asm volatile("cp.async.commit_group;" ::: "memory")
#define CP_WAIT(n)  asm volatile("cp.async.wait_group %0;" :: "n"(n) : "memory")

// ---------------- kernel 0a: T5 relative bias table (pre-scaled for exp2) ------
__global__ void bias_table_kernel(const float* __restrict__ rel_emb) {
    int idx = blockIdx.x * blockDim.x + threadIdx.x;
    if (idx >= HEADS * NREL) return;
    int h = idx / NREL;
    int rel = idx % NREL - (SEQ - 1);   // rel = j - i
    int n = -rel;                        // i - j
    int ret = 0;
    if (n < 0) { ret = 16; n = -n; }
    int bucket;
    if (n < 8) {
        bucket = ret + n;
    } else {
        int v = 8 + (int)(logf((float)n / 8.0f) / logf(16.0f) * 8.0f);
        v = min(v, 15);
        bucket = ret + v;
    }
    g_bias[idx] = (rel_emb[bucket * HEADS + h] - 12.0f) * LOG2E;
}

// ---------------- kernel 0b: round X to tf32 ----------------
__global__ __launch_bounds__(256) void round_x_kernel(const float* __restrict__ X) {
    int i = blockIdx.x * 256 + threadIdx.x;
    float4 v = ((const float4*)X)[i];
    v.x = to_tf32(v.x); v.y = to_tf32(v.y); v.z = to_tf32(v.z); v.w = to_tf32(v.w);
    ((float4*)g_xr)[i] = v;
}

// ---------------- kernel 0c: transpose + round weights --------------------------
__global__ void transpose_round(int dsel, size_t doff, const float* __restrict__ src, int N) {
    __shared__ float t[32][33];
    float* dst = (dsel == 0 ? g_wt : g_wot) + doff;
    int n0 = blockIdx.x * 32, k0 = blockIdx.y * 32;
    int tx = threadIdx.x, ty = threadIdx.y;
#pragma unroll
    for (int j = 0; j < 32; j += 8)
        t[ty + j][tx] = to_tf32(src[(size_t)(k0 + ty + j) * N + n0 + tx]);
    __syncthreads();
#pragma unroll
    for (int j = 0; j < 32; j += 8)
        dst[(size_t)(n0 + ty + j) * DIM + k0 + tx] = t[tx][ty + j];
}

// ======================================================================
// GEMM core (unchanged from 746us run): CTA 128x128, cp.async double-buffered.
// ======================================================================
#define GR 36
#define ABUF(b)  ((b) * 4608)
#define BBUF(b)  (9216 + (b) * 4608)
#define G_SMEM_BYTES 73728

__device__ __forceinline__ void g_stage(uint32_t sbase, int buf,
                                        const float* __restrict__ Asrc,
                                        const float* __restrict__ Bsrc,
                                        int kt, int tid) {
    const int m = tid >> 1, half = tid & 1;
    const float* as = Asrc + (size_t)m * DIM + kt * 32 + half * 16;
    uint32_t ad = sbase + buf * 18432 + m * 144 + half * 64;
#pragma unroll
    for (int c = 0; c < 4; c++) cp16(ad + c * 16, as + c * 4);
    const float* bs = Bsrc + (size_t)m * DIM + kt * 32 + half * 16;
    uint32_t bd = sbase + 36864 + buf * 18432 + m * 144 + half * 64;
#pragma unroll
    for (int c = 0; c < 4; c++) cp16(bd + c * 16, bs + c * 4);
}

__device__ __forceinline__ void g_mainloop(float* smem, uint32_t sbase,
                                           const float* Asrc, const float* Bsrc,
                                           float acc[2][8][4],
                                           int tid, int wm, int wn, int g, int tg) {
    g_stage(sbase, 0, Asrc, Bsrc, 0, tid);
    CP_COMMIT();
    for (int kt = 0; kt < 32; kt++) {
        int buf = kt & 1;
        if (kt + 1 < 32) {
            g_stage(sbase, buf ^ 1, Asrc, Bsrc, kt + 1, tid);
            CP_COMMIT();
            CP_WAIT(1);
        } else {
            CP_WAIT(0);
        }
        __syncthreads();
        const float* As = smem + ABUF(buf);
        const float* Bs = smem + BBUF(buf);
#pragma unroll
        for (int kk = 0; kk < 4; kk++) {
            float aF[2][4]; float bF[8][2];
#pragma unroll
            for (int mt = 0; mt < 2; mt++) {
                int r = wm * 32 + mt * 16 + g;
                aF[mt][0] = As[r * GR + kk * 8 + tg];
                aF[mt][1] = As[(r + 8) * GR + kk * 8 + tg];
                aF[mt][2] = As[r * GR + kk * 8 + tg + 4];
                aF[mt][3] = As[(r + 8) * GR + kk * 8 + tg + 4];
            }
#pragma unroll
            for (int nt = 0; nt < 8; nt++) {
                int c = wn * 64 + nt * 8 + g;
                bF[nt][0] = Bs[c * GR + kk * 8 + tg];
                bF[nt][1] = Bs[c * GR + kk * 8 + tg + 4];
            }
#pragma unroll
            for (int mt = 0; mt < 2; mt++)
#pragma unroll
                for (int nt = 0; nt < 8; nt++)
                    mma8(acc[mt][nt], aF[mt][0], aF[mt][1], aF[mt][2], aF[mt][3],
                         bF[nt][0], bF[nt][1]);
        }
        __syncthreads();
    }
}

// ---------------- kernel 1: fused QKV projection ----------------
__global__ __launch_bounds__(256, 2) void gemm_qkv2() {
    extern __shared__ __align__(16) float smem[];
    uint32_t sbase = smem_u32(smem);
    const int tid = threadIdx.x;
    const int warp = tid >> 5, lane = tid & 31;
    const int wm = warp >> 1, wn = warp & 1;
    const int g = lane >> 2, tg = lane & 3;
    const int row0 = blockIdx.y * 128, ncol0 = blockIdx.x * 128;

    float acc[2][8][4];
#pragma unroll
    for (int a = 0; a < 2; a++)
#pragma unroll
        for (int b = 0; b < 8; b++)
#pragma unroll
            for (int c = 0; c < 4; c++) acc[a][b][c] = 0.f;

    g_mainloop(smem, sbase, g_xr + (size_t)row0 * DIM, g_wt + (size_t)ncol0 * DIM,
               acc, tid, wm, wn, g, tg);

    // scatter into (b,h,n,d), tf32-rounded (q *0.125: exact pow2 scale commutes
    // bit-exactly with tf32 rounding)
#pragma unroll
    for (int mt = 0; mt < 2; mt++) {
        int r0 = row0 + wm * 32 + mt * 16 + g;
        int bb = r0 >> 11;
        int ii = r0 & 2047;
#pragma unroll
        for (int nt = 0; nt < 8; nt++) {
            int c0 = ncol0 + wn * 64 + nt * 8 + 2 * tg;
            int reg2 = c0 >> 10;          // 0:q 1:k 2:v
            int c = c0 & 1023;
            int h = c >> 6, dd = c & 63;
            float* base = (reg2 == 0) ? g_q : ((reg2 == 1) ? g_k : g_v);
            float s = (reg2 == 0) ? 0.125f : 1.0f;
            size_t o0 = (((size_t)(bb * HEADS + h) * SEQ) + ii) * DHEAD + dd;
            *(float2*)(base + o0) =
                make_float2(to_tf32(acc[mt][nt][0]) * s, to_tf32(acc[mt][nt][1]) * s);
            *(float2*)(base + o0 + 512) =
                make_float2(to_tf32(acc[mt][nt][2]) * s, to_tf32(acc[mt][nt][3]) * s);
        }
    }
}

// ---------------- kernel 3: output projection + bias ----------------
__global__ __launch_bounds__(256, 2) void gemm_out2(
    const float* __restrict__ bo, float* __restrict__ out) {
    extern __shared__ __align__(16) float smem[];
    uint32_t sbase = smem_u32(smem);
    const int tid = threadIdx.x;
    const int warp = tid >> 5, lane = tid & 31;
    const int wm = warp >> 1, wn = warp & 1;
    const int g = lane >> 2, tg = lane & 3;
    const int row0 = blockIdx.y * 128, ncol0 = blockIdx.x * 128;

    float acc[2][8][4];
#pragma unroll
    for (int a = 0; a < 2; a++)
#pragma unroll
        for (int b = 0; b < 8; b++)
#pragma unroll
            for (int c = 0; c < 4; c++) acc[a][b][c] = 0.f;

    g_mainloop(smem, sbase, g_attn + (size_t)row0 * INNER, g_wot + (size_t)ncol0 * DIM,
               acc, tid, wm, wn, g, tg);

#pragma unroll
    for (int mt = 0; mt < 2; mt++) {
        int r0 = row0 + wm * 32 + mt * 16 + g;
#pragma unroll
        for (int nt = 0; nt < 8; nt++) {
            int c0 = ncol0 + wn * 64 + nt * 8 + 2 * tg;
            float b0 = bo[c0], b1 = bo[c0 + 1];
            *(float2*)(out + (size_t)r0 * DIM + c0)       = make_float2(acc[mt][nt][0] + b0, acc[mt][nt][1] + b1);
            *(float2*)(out + (size_t)(r0 + 8) * DIM + c0) = make_float2(acc[mt][nt][2] + b0, acc[mt][nt][3] + b1);
        }
    }
}

// ======================================================================
// kernel 2: flash attention — 256 q-rows/CTA (proven best), with K/V
// REGISTER PREFETCH: next tile's LDGs issue right after the staging barrier,
// overlapping ~400cyc memory latency with MMA+softmax compute.
// Inputs pre-rounded tf32 (q pre-scaled 0.125): zero cvts in staging.
// ======================================================================
#define FROW 72
#define FLASH_SMEM_FLOATS ((256 + 256 + 64 + 64) * FROW)

__global__ __launch_bounds__(256) void flash_attn()
{
    extern __shared__ __align__(16) float fsmem[];
    float* Qs = fsmem;             // 256 x 72
    float* Ps = Qs + 256 * FROW;   // 256 x 72
    float* Ks = Ps + 256 * FROW;   // 64 x 72
    float* Vs = Ks + 64 * FROW;    // 64 x 72

    const int qb = blockIdx.x, bh = blockIdx.y;
    const int b = bh >> 4, h = bh & 15;
    const int tid = threadIdx.x, warp = tid >> 5, lane = tid & 31;
    const int g = lane >> 2, tg = lane & 3;

    const float* qptr = g_q + ((size_t)bh * SEQ + qb * 256) * DHEAD;
    const float* kptr = g_k + (size_t)bh * SEQ * DHEAD;
    const float* vptr = g_v + (size_t)bh * SEQ * DHEAD;

#pragma unroll
    for (int i = 0; i < 16; i++) {
        int f = tid + i * 256;
        int row = f >> 4, d0 = (f & 15) << 2;
        float4 v = *(const float4*)(qptr + row * DHEAD + d0);
        float* dst = Qs + row * FROW;
        int q4 = d0 >> 2;
        dst[q4]            = v.x;
        dst[16 + q4]       = v.y;
        dst[(32 + q4) ^ 4] = v.z;
        dst[(48 + q4) ^ 4] = v.w;
    }

    float oa[2][8][4];
#pragma unroll
    for (int mt = 0; mt < 2; mt++)
#pragma unroll
        for (int nt = 0; nt < 8; nt++)
#pragma unroll
            for (int c = 0; c < 4; c++) oa[mt][nt][c] = 0.f;
    float lsum[2][2] = {{0.f, 0.f}, {0.f, 0.f}};

    const float* btab = g_bias + h * NREL + (SEQ - 1);
    const int iG = qb * 256 + warp * 32 + g;

    // prefetch tile 0 into registers
    float4 kR[4], vR[4];
#pragma unroll
    for (int i = 0; i < 4; i++) {
        int f = tid + i * 256;
        int key = f >> 4, d0 = (f & 15) << 2;
        kR[i] = *(const float4*)(kptr + key * DHEAD + d0);
        vR[i] = *(const float4*)(vptr + key * DHEAD + d0);
    }

    for (int t = 0; t < SEQ / 64; t++) {
        // stage K/V tile from prefetch registers (no global latency here)
#pragma unroll
        for (int i = 0; i < 4; i++) {
            int f = tid + i * 256;
            int key = f >> 4, d0 = (f & 15) << 2;
            int q4 = d0 >> 2;
            float* kd = Ks + key * FROW;
            kd[q4]            = kR[i].x;
            kd[16 + q4]       = kR[i].y;
            kd[(32 + q4) ^ 4] = kR[i].z;
            kd[(48 + q4) ^ 4] = kR[i].w;
            int vpos = (((key & 3) << 4) + (key >> 2)) ^ ((key & 2) << 1);
            Vs[(d0 + 0) * FROW + vpos] = vR[i].x;
            Vs[(d0 + 1) * FROW + vpos] = vR[i].y;
            Vs[(d0 + 2) * FROW + vpos] = vR[i].z;
            Vs[(d0 + 3) * FROW + vpos] = vR[i].w;
        }
        __syncthreads();
        // issue next tile's loads; latency hides under compute below
        if (t + 1 < SEQ / 64) {
#pragma unroll
            for (int i = 0; i < 4; i++) {
                int f = tid + i * 256;
                int key = f >> 4, d0 = (f & 15) << 2;
                kR[i] = *(const float4*)(kptr + (size_t)(t + 1) * 64 * DHEAD + key * DHEAD + d0);
                vR[i] = *(const float4*)(vptr + (size_t)(t + 1) * 64 * DHEAD + key * DHEAD + d0);
            }
        }

        float sc[2][8][4];
#pragma unroll
        for (int mt = 0; mt < 2; mt++)
#pragma unroll
            for (int nt = 0; nt < 8; nt++)
#pragma unroll
                for (int c = 0; c < 4; c++) sc[mt][nt][c] = 0.f;
#pragma unroll
        for (int p = 0; p < 4; p++) {
            int off = (tg * 16 + 4 * p) ^ ((tg & 2) << 1);
            float4 qLo[2], qHi[2], kf[8];
#pragma unroll
            for (int mt = 0; mt < 2; mt++) {
                int r = warp * 32 + mt * 16 + g;
                qLo[mt] = *(const float4*)(Qs + r * FROW + off);
                qHi[mt] = *(const float4*)(Qs + (r + 8) * FROW + off);
            }
#pragma unroll
            for (int nt = 0; nt < 8; nt++)
                kf[nt] = *(const float4*)(Ks + (nt * 8 + g) * FROW + off);
#pragma unroll
            for (int mt = 0; mt < 2; mt++)
#pragma unroll
                for (int nt = 0; nt < 8; nt++) {
                    mma8(sc[mt][nt], qLo[mt].x, qHi[mt].x, qLo[mt].y, qHi[mt].y, kf[nt].x, kf[nt].y);
                    mma8(sc[mt][nt], qLo[mt].z, qHi[mt].z, qLo[mt].w, qHi[mt].w, kf[nt].z, kf[nt].w);
                }
        }

#pragma unroll
        for (int mt = 0; mt < 2; mt++) {
            int r0 = warp * 32 + mt * 16 + g;
            int i0 = iG + mt * 16;
            const float* bt0 = btab + t * 64 - i0;
            const float* bt1 = bt0 - 8;
#pragma unroll
            for (int nt = 0; nt < 8; nt++) {
                int c = nt * 8 + 2 * tg;
                int pos0 = (((c & 3) << 4) + (c >> 2)) ^ ((c & 2) << 1);
                int c1 = c + 1;
                int pos1 = ((((c1) & 3) << 4) + (c1 >> 2)) ^ ((c1 & 2) << 1);
                float p0 = to_tf32(ex2f(fmaf(sc[mt][nt][0], LOG2E, bt0[c])));
                float p1 = to_tf32(ex2f(fmaf(sc[mt][nt][1], LOG2E, bt0[c1])));
                float p2 = to_tf32(ex2f(fmaf(sc[mt][nt][2], LOG2E, bt1[c])));
                float p3 = to_tf32(ex2f(fmaf(sc[mt][nt][3], LOG2E, bt1[c1])));
                lsum[mt][0] += p0 + p1;
                lsum[mt][1] += p2 + p3;
                Ps[r0 * FROW + pos0]       = p0;
                Ps[r0 * FROW + pos1]       = p1;
                Ps[(r0 + 8) * FROW + pos0] = p2;
                Ps[(r0 + 8) * FROW + pos1] = p3;
            }
        }
        __syncwarp();

#pragma unroll
        for (int p = 0; p < 4; p++) {
            int off = (tg * 16 + 4 * p) ^ ((tg & 2) << 1);
            float4 pLo[2], pHi[2], vf[8];
#pragma unroll
            for (int mt = 0; mt < 2; mt++) {
                int r = warp * 32 + mt * 16 + g;
                pLo[mt] = *(const float4*)(Ps + r * FROW + off);
                pHi[mt] = *(const float4*)(Ps + (r + 8) * FROW + off);
            }
#pragma unroll
            for (int nt = 0; nt < 8; nt++)
                vf[nt] = *(const float4*)(Vs + (nt * 8 + g) * FROW + off);
#pragma unroll
            for (int mt = 0; mt < 2; mt++)
#pragma unroll
                for (int nt = 0; nt < 8; nt++) {
                    mma8(oa[mt][nt], pLo[mt].x, pHi[mt].x, pLo[mt].y, pHi[mt].y, vf[nt].x, vf[nt].y);
                    mma8(oa[mt][nt], pLo[mt].z, pHi[mt].z, pLo[mt].w, pHi[mt].w, vf[nt].z, vf[nt].w);
                }
        }
        __syncthreads();
    }

    // epilogue: normalize, tf32-round (gemm_out consumes raw), write (b, n, h*d)
    float* obase = g_attn + (size_t)b * SEQ * INNER + h * DHEAD;
#pragma unroll
    for (int mt = 0; mt < 2; mt++) {
        float l0 = lsum[mt][0], l1 = lsum[mt][1];
        l0 += __shfl_xor_sync(0xffffffffu, l0, 1);
        l0 += __shfl_xor_sync(0xffffffffu, l0, 2);
        l1 += __shfl_xor_sync(0xffffffffu, l1, 1);
        l1 += __shfl_xor_sync(0xffffffffu, l1, 2);
        float il0 = 1.f / l0, il1 = 1.f / l1;
        int rg = qb * 256 + warp * 32 + mt * 16 + g;
#pragma unroll
        for (int nt = 0; nt < 8; nt++) {
            int col = nt * 8 + 2 * tg;
            *(float2*)(obase + (size_t)rg * INNER + col) =
                make_float2(to_tf32(oa[mt][nt][0] * il0), to_tf32(oa[mt][nt][1] * il0));
            *(float2*)(obase + (size_t)(rg + 8) * INNER + col) =
                make_float2(to_tf32(oa[mt][nt][2] * il1), to_tf32(oa[mt][nt][3] * il1));
        }
    }
}

// ---------------- launch ----------------
extern "C" void kernel_launch(void* const* d_in, const int* in_sizes, int n_in,
                              void* d_out, int out_size)
{
    const float* x    = (const float*)d_in[0];
    const float* Wq   = (const float*)d_in[1];
    const float* Wkv  = (const float*)d_in[2];
    const float* Wo   = (const float*)d_in[3];
    const float* bo   = (const float*)d_in[4];
    const float* rel  = (const float*)d_in[5];
    float* out = (float*)d_out;

    const int flash_smem = FLASH_SMEM_FLOATS * (int)sizeof(float); // 184,320 B
    cudaFuncSetAttribute(flash_attn, cudaFuncAttributeMaxDynamicSharedMemorySize, flash_smem);
    cudaFuncSetAttribute(gemm_qkv2, cudaFuncAttributeMaxDynamicSharedMemorySize, G_SMEM_BYTES);
    cudaFuncSetAttribute(gemm_out2, cudaFuncAttributeMaxDynamicSharedMemorySize, G_SMEM_BYTES);

    // prep: bias table, rounded X, transposed+rounded weights
    bias_table_kernel<<<(HEADS * NREL + 255) / 256, 256>>>(rel);
    round_x_kernel<<<BATCH * SEQ * DIM / 4 / 256, 256>>>(x);
    {
        dim3 tb(32, 8);
        transpose_round<<<dim3(DIM / 32, DIM / 32), tb>>>(0, 0, Wq, INNER);
        transpose_round<<<dim3(2 * INNER / 32, DIM / 32), tb>>>(0, (size_t)INNER * DIM, Wkv, 2 * INNER);
        transpose_round<<<dim3(DIM / 32, DIM / 32), tb>>>(1, 0, Wo, DIM);
    }

    gemm_qkv2<<<dim3(24, 32), 256, G_SMEM_BYTES>>>();
    flash_attn<<<dim3(8, 32), 256, flash_smem>>>();
    gemm_out2<<<dim3(8, 32), 256, G_SMEM_BYTES>>>(bo, out);
}